// round 16
// baseline (speedup 1.0000x reference)
#include <cuda_runtime.h>
#include <cuda_fp16.h>
#include <math.h>
#include <stdint.h>

// Problem constants
#define BB 32
#define NN 4096
#define DD 512
#define CC 64
#define RTOT (BB*NN)          // 131072 rows
#define MT 64                 // rows per GEMM tile
#define NT64 (RTOT/MT)        // 2048
#define XPH 520               // x_s pitch in halves: 260 words ≡ 4 (mod 32) -> conflict-free
#define APH 520               // anchor pitch in halves
#define DP 65                 // dots pitch in floats
#define CHUNK 128             // rows per feature chunk
#define NCHUNK (NN/CHUNK)     // 32

// Device scratch (allocation-free rule: __device__ globals)
__device__ float  g_sw[(size_t)RTOT*CC];          // score*invnorm*valid, 32 MiB
__device__ __half g_xh[(size_t)RTOT*DD];          // x in fp16 (written by main), 128 MiB
__device__ int    g_counts[BB*CC];
__device__ int    g_index[BB];
__device__ float  g_part[(size_t)BB*NCHUNK*DD];   // 2 MiB

// mask may be int64 (jax x64) or int32. Values in [1,4096]: if int64 LE,
// word 1 (high half of elem 0) is 0.
__device__ __forceinline__ int decode_mask(const int* mr, int b) {
    return (mr[1] == 0) ? mr[2*b] : mr[b];
}

// fp16-accumulate mma: C/D packed as 2x half2 registers
__device__ __forceinline__ void mma_f16acc(unsigned& c0, unsigned& c1,
                                           unsigned a0, unsigned a1, unsigned a2, unsigned a3,
                                           unsigned b0, unsigned b1) {
    asm volatile("mma.sync.aligned.m16n8k16.row.col.f16.f16.f16.f16 "
                 "{%0,%1}, {%2,%3,%4,%5}, {%6,%7}, {%0,%1};"
                 : "+r"(c0), "+r"(c1)
                 : "r"(a0), "r"(a1), "r"(a2), "r"(a3), "r"(b0), "r"(b1));
}

__global__ __launch_bounds__(512, 1)
void main_kernel(const float* __restrict__ x, const int* __restrict__ maskr,
                 const float* __restrict__ anchors) {
    extern __shared__ char smem[];
    __half*   a_h    = (__half*)smem;                    // [CC][APH] anchors fp16
    __half*   x_h    = a_h + CC*APH;                     // [MT][XPH] x tile fp16
    float*    dots_s = (float*)(x_h + MT*XPH);           // [MT][DP]
    float*    anorm_s= dots_s + MT*DP;                   // [CC]
    float*    norm_s = anorm_s + CC;                     // [MT]
    int*      mask_s = (int*)(norm_s + MT);              // [BB]
    int*      pref_s = mask_s + BB;                      // [BB+1]

    const int tid  = threadIdx.x;
    const int lane = tid & 31, warp = tid >> 5;           // 16 warps

    // ---- anchors -> smem fp16, [c][k] pitch APH ----
    for (int i = tid; i < CC*DD; i += 512) {
        int c = i >> 9, k = i & (DD-1);
        a_h[c*APH + k] = __float2half_rn(anchors[i]);
    }
    if (tid < BB) mask_s[tid] = decode_mask(maskr, tid);
    if (tid < CC) {
        float s = 0.f;
        const float* ar = anchors + (size_t)tid*DD;
        #pragma unroll 8
        for (int k = 0; k < DD; k++) { float q = ar[k]; s = fmaf(q, q, s); }
        anorm_s[tid] = s;
    }
    __syncthreads();
    if (tid == 0) {
        int acc = 0;
        #pragma unroll
        for (int i = 0; i < BB; i++) {
            pref_s[i] = acc;
            acc += (mask_s[i] + MT - 1) >> 6;    // 64-row tiles in batch i
        }
        pref_s[BB] = acc;
    }
    __syncthreads();
    const int V = pref_s[BB];

    // warp decomposition: ms(4) x ns(4), full K per warp
    const int gid = lane >> 2, tig = lane & 3;
    const int mbase = (warp & 3) * 16;
    const int nb0   = (warp >> 2) * 16;

    // load mapping: row r = tid>>3 (0..63), slot base = tid&7 (+8j, j=0..15)
    const int lrow  = tid >> 3;
    const int lslot = tid & 7;

    // map compact valid-index -> (batch, rowbase) via binary search over pref_s
    auto map_vi = [&](int vi, int& bout) -> int {
        int lo = 0, hi = BB - 1;
        #pragma unroll
        for (int s = 0; s < 5; s++) {
            int mid = (lo + hi + 1) >> 1;
            if (pref_s[mid] <= vi) lo = mid; else hi = mid - 1;
        }
        bout = lo;
        return lo*NN + (vi - pref_s[lo])*MT;
    };

    // ---- prefetch first work unit ----
    int vi = blockIdx.x;
    int b = 0, rowbase = 0;
    float4 v[16];
    if (vi < V) {
        rowbase = map_vi(vi, b);
        const float4* xg = (const float4*)(x + (size_t)rowbase*DD) + lrow*128 + lslot;
        #pragma unroll
        for (int j = 0; j < 16; j++) v[j] = xg[8*j];
    }

    while (vi < V) {
        // ---- store tile to smem (fp16) + mirror to g_xh + row norm ----
        float ns = 0.f;
        {
            char* xrow = (char*)x_h + lrow*(XPH*2);
            uint2* xhrow = (uint2*)(g_xh + (size_t)(rowbase + lrow)*DD);
            #pragma unroll
            for (int j = 0; j < 16; j++) {
                float4 q = v[j];
                __half2 h01 = __floats2half2_rn(q.x, q.y);
                __half2 h23 = __floats2half2_rn(q.z, q.w);
                uint2 st;
                st.x = *(unsigned*)&h01;
                st.y = *(unsigned*)&h23;
                int slot = lslot + 8*j;
                *(uint2*)(xrow + slot*8) = st;
                xhrow[slot] = st;
                ns = fmaf(q.x,q.x, fmaf(q.y,q.y, fmaf(q.z,q.z, fmaf(q.w,q.w, ns))));
            }
        }
        #pragma unroll
        for (int o = 4; o; o >>= 1) ns += __shfl_xor_sync(0xffffffffu, ns, o);
        if ((lane & 7) == 0) norm_s[lrow] = ns;
        __syncthreads();

        // ---- prefetch next work unit (overlaps with mma) ----
        const int nvi = vi + gridDim.x;
        int nb = 0, nrowbase = 0;
        if (nvi < V) {
            nrowbase = map_vi(nvi, nb);
            const float4* xg = (const float4*)(x + (size_t)nrowbase*DD) + lrow*128 + lslot;
            #pragma unroll
            for (int j = 0; j < 16; j++) v[j] = xg[8*j];
        }

        // ---- fp16 mma over full K=512: 32 k-steps, fp16-acc chains of 4 ----
        float d00=0,d01=0,d02=0,d03=0, d10=0,d11=0,d12=0,d13=0;
        const __half* xa  = x_h + (mbase + gid)*XPH + 2*tig;
        const __half* b0p = a_h + (nb0 + gid)*APH     + 2*tig;
        const __half* b1p = a_h + (nb0 + gid + 8)*APH + 2*tig;
        #pragma unroll
        for (int g = 0; g < 8; g++) {
            unsigned e00=0, e01=0, e10=0, e11=0;
            #pragma unroll
            for (int s = 0; s < 4; s++) {
                const int k0 = (g*4 + s)*16;
                unsigned a0 = *(const unsigned*)(xa + k0);
                unsigned a1 = *(const unsigned*)(xa + 8*XPH + k0);
                unsigned a2 = *(const unsigned*)(xa + k0 + 8);
                unsigned a3 = *(const unsigned*)(xa + 8*XPH + k0 + 8);
                unsigned b00 = *(const unsigned*)(b0p + k0);
                unsigned b01 = *(const unsigned*)(b0p + k0 + 8);
                unsigned b10 = *(const unsigned*)(b1p + k0);
                unsigned b11 = *(const unsigned*)(b1p + k0 + 8);
                mma_f16acc(e00, e01, a0,a1,a2,a3, b00,b01);
                mma_f16acc(e10, e11, a0,a1,a2,a3, b10,b11);
            }
            {
                float2 f;
                f = __half22float2(*(__half2*)&e00); d00 += f.x; d01 += f.y;
                f = __half22float2(*(__half2*)&e01); d02 += f.x; d03 += f.y;
                f = __half22float2(*(__half2*)&e10); d10 += f.x; d11 += f.y;
                f = __half22float2(*(__half2*)&e11); d12 += f.x; d13 += f.y;
            }
        }
        {
            const int r0 = mbase + gid, r1 = r0 + 8, cb = 2*tig;
            dots_s[r0*DP + nb0 + cb]         = d00;
            dots_s[r0*DP + nb0 + cb + 1]     = d01;
            dots_s[r1*DP + nb0 + cb]         = d02;
            dots_s[r1*DP + nb0 + cb + 1]     = d03;
            dots_s[r0*DP + nb0 + 8 + cb]     = d10;
            dots_s[r0*DP + nb0 + 8 + cb + 1] = d11;
            dots_s[r1*DP + nb0 + 8 + cb]     = d12;
            dots_s[r1*DP + nb0 + 8 + cb + 1] = d13;
        }
        __syncthreads();

        // ---- epilogue: 4 rows per warp; softmax without max-shift ----
        // (invd <= ~0.09 always since ||anchor|| >= ~12, ||xn|| = 1 -> no overflow)
        #pragma unroll
        for (int u = 0; u < 4; u++) {
            const int m = warp*4 + u;
            const int row = rowbase + m;
            const int n = row & (NN-1);
            const bool valid = n < mask_s[b];
            const float n2  = norm_s[m];
            const float inv = 1.f / fmaxf(sqrtf(n2), 1e-12f);
            const float sxn2 = n2 * inv * inv;
            const int cA = lane, cB = lane + 32;
            const float dA = dots_s[m*DP + cA];
            const float dB = dots_s[m*DP + cB];
            const float sqA = sxn2 + anorm_s[cA] - 2.f*dA*inv;
            const float sqB = sxn2 + anorm_s[cB] - 2.f*dB*inv;
            const float idA = rsqrtf(fmaxf(sqA, 1e-30f));
            const float idB = rsqrtf(fmaxf(sqB, 1e-30f));
            const float eA = __expf(idA), eB = __expf(idB);
            float ss = eA + eB;
            #pragma unroll
            for (int o = 16; o; o >>= 1) ss += __shfl_xor_sync(0xffffffffu, ss, o);
            const float rs = 1.f / ss;
            const size_t base = (size_t)row * CC;
            g_sw[base + cA] = valid ? eA*rs*inv : 0.f;
            g_sw[base + cB] = valid ? eB*rs*inv : 0.f;
            float bv; int bi;
            if (idB > idA) { bv = idB; bi = cB; } else { bv = idA; bi = cA; }
            #pragma unroll
            for (int o = 16; o; o >>= 1) {
                float ov = __shfl_xor_sync(0xffffffffu, bv, o);
                int   oi = __shfl_xor_sync(0xffffffffu, bi, o);
                if (ov > bv || (ov == bv && oi < bi)) { bv = ov; bi = oi; }
            }
            if (lane == 0 && valid) atomicAdd(&g_counts[b*CC + bi], 1);
        }
        __syncthreads();
        vi = nvi; b = nb; rowbase = nrowbase;
    }
}

// argmax of counts per batch; also resets counts for the next graph replay
__global__ void index_kernel() {
    __shared__ int sv[CC], si[CC];
    const int b = blockIdx.x, c = threadIdx.x;
    sv[c] = g_counts[b*CC + c]; si[c] = c;
    g_counts[b*CC + c] = 0;
    __syncthreads();
    for (int o = 32; o; o >>= 1) {
        if (c < o) {
            if (sv[c+o] > sv[c] || (sv[c+o] == sv[c] && si[c+o] < si[c])) {
                sv[c] = sv[c+o]; si[c] = si[c+o];
            }
        }
        __syncthreads();
    }
    if (c == 0) g_index[b] = si[0];
}

// reads fp16 x copy (half traffic); thread tid covers d = {2*tid, 2*tid+1}
__global__ __launch_bounds__(256)
void feat_part_kernel(const int* __restrict__ maskr) {
    const int b = blockIdx.y, ch = blockIdx.x;
    const int tid = threadIdx.x;
    __shared__ float w_s[CHUNK];
    __shared__ int s_idx, s_nv;
    if (tid == 0) {
        s_idx = g_index[b];
        int nv = decode_mask(maskr, b) - ch*CHUNK;
        s_nv = nv < 0 ? 0 : (nv > CHUNK ? CHUNK : nv);
    }
    __syncthreads();
    const int nv = s_nv;
    float* gp = g_part + ((size_t)b*NCHUNK + ch)*DD;
    if (nv == 0) {
        ((float2*)gp)[tid] = make_float2(0.f, 0.f);
        return;
    }
    const int idx = s_idx;
    const int rowbase = b*NN + ch*CHUNK;
    if (tid < CHUNK) w_s[tid] = (tid < nv) ? g_sw[(size_t)(rowbase + tid)*CC + idx] : 0.f;
    __syncthreads();
    float ax = 0.f, ay = 0.f;
    const __half2* xb = (const __half2*)(g_xh + (size_t)rowbase*DD) + tid;
    int r = 0;
    for (; r + 16 <= nv; r += 16) {
        __half2 vv[16];
        #pragma unroll
        for (int u = 0; u < 16; u++) vv[u] = xb[(size_t)(r+u)*256];
        #pragma unroll
        for (int u = 0; u < 16; u++) {
            float2 f = __half22float2(vv[u]);
            float w = w_s[r+u];
            ax = fmaf(f.x, w, ax);
            ay = fmaf(f.y, w, ay);
        }
    }
    for (; r < nv; r++) {
        float2 f = __half22float2(xb[(size_t)r*256]);
        float w = w_s[r];
        ax = fmaf(f.x, w, ax);
        ay = fmaf(f.y, w, ay);
    }
    ((float2*)gp)[tid] = make_float2(ax, ay);
}

// 256 blocks x 256 threads: 64 outputs/block, 4-way chunk split + smem combine
__global__ void feat_reduce_kernel(float* __restrict__ out) {
    __shared__ float sm[256];
    const int o = threadIdx.x & 63, s = threadIdx.x >> 6;
    const int gidx = blockIdx.x*64 + o;     // 0..16383
    const int b = gidx >> 9, d = gidx & 511;
    const float* gp = g_part + ((size_t)b*NCHUNK + s*8)*DD + d;
    float sum = 0.f;
    #pragma unroll
    for (int i = 0; i < 8; i++) sum += gp[i*DD];
    sm[threadIdx.x] = sum;
    __syncthreads();
    if (s == 0) out[gidx] = sm[o] + sm[64 + o] + sm[128 + o] + sm[192 + o];
}

extern "C" void kernel_launch(void* const* d_in, const int* in_sizes, int n_in,
                              void* d_out, int out_size) {
    const float* x       = (const float*)d_in[0];
    const int*   mask    = (const int*)d_in[1];
    const float* anchors = (const float*)d_in[2];
    float* out = (float*)d_out;

    const size_t smem = (size_t)(CC*APH + MT*XPH)*sizeof(__half)
                      + (size_t)(MT*DP + CC + MT)*sizeof(float)
                      + (2*BB + 1)*sizeof(int);   // ~150 KB
    cudaFuncSetAttribute(main_kernel, cudaFuncAttributeMaxDynamicSharedMemorySize, (int)smem);

    main_kernel<<<152, 512, smem>>>(x, mask, anchors);
    index_kernel<<<BB, CC>>>();
    dim3 g(NCHUNK, BB);
    feat_part_kernel<<<g, 256>>>(mask);
    feat_reduce_kernel<<<256, 256>>>(out);
}